// round 1
// baseline (speedup 1.0000x reference)
#include <cuda_runtime.h>

#define W      256
#define IMGPIX 65536
#define OW     246
#define KS     11
#define STRIP  44
#define NSTRIPS 6
#define RING   16

// per-block partial sums (6*496 = 2976 slots used; all used slots rewritten every launch)
__device__ float d_partials[8192];

__device__ __forceinline__ float4 f4fma(float g, float4 p, float4 a) {
    a.x = fmaf(g, p.x, a.x);
    a.y = fmaf(g, p.y, a.y);
    a.z = fmaf(g, p.z, a.z);
    a.w = fmaf(g, p.w, a.w);
    return a;
}

__global__ __launch_bounds__(256, 2)
void ssim_main(const float* __restrict__ X, const float* __restrict__ Y) {
    // 11-tap gaussian, sigma=1.5 (torchmetrics default), normalized
    constexpr float G[11] = {
        0.00102838f, 0.00759876f, 0.03600077f, 0.10936069f, 0.21300554f,
        0.26601173f,
        0.21300554f, 0.10936069f, 0.03600077f, 0.00759876f, 0.00102838f
    };
    constexpr float C1 = 1e-4f;   // (0.01*1)^2
    constexpr float C2 = 9e-4f;   // (0.03*1)^2

    extern __shared__ float sm[];
    // product ring: 4 channels x RING rows x 256 cols
    float* p_s  = sm;
    float* p_d  = sm + 4096;
    float* p_ss = sm + 8192;
    float* p_dd = sm + 12288;
    // vertical-blur buffers: 4 channels x 4 rows x 256 cols
    float* v_s  = sm + 16384;
    float* v_d  = sm + 17408;
    float* v_ss = sm + 18432;
    float* v_dd = sm + 19456;
    float* red  = sm + 20480;   // 32 floats reduction scratch (also OOB-read pad)

    const int t   = threadIdx.x;
    const int img = blockIdx.y;
    const int r0  = blockIdx.x * STRIP;
    const int rows = min(STRIP, OW - r0);

    const float* __restrict__ x = X + (size_t)img * IMGPIX;
    const float* __restrict__ y = Y + (size_t)img * IMGPIX;

    // preload first 14 input rows (rows r0 .. r0+13, all < 256)
    #pragma unroll 2
    for (int i = 0; i < 14; i++) {
        const int r = r0 + i;
        const float xv = x[r * W + t];
        const float yv = y[r * W + t];
        const float s = xv + yv, d = xv - yv;
        const int slot = (r & (RING - 1)) * W + t;
        p_s[slot]  = s;
        p_d[slot]  = d;
        p_ss[slot] = s * s;
        p_dd[slot] = d * d;
    }

    float acc = 0.0f;
    const int g  = t & 63;   // column group (4 cols)
    const int rr = t >> 6;   // row within 4-row group

    for (int g0 = 0; g0 < rows; g0 += 4) {
        const int o0 = r0 + g0;   // first output row of this group

        if (g0 > 0) {
            // bring in the 4 new input rows o0+10 .. o0+13
            #pragma unroll
            for (int i = 0; i < 4; i++) {
                const int r = o0 + 10 + i;
                if (r < 256) {
                    const float xv = x[r * W + t];
                    const float yv = y[r * W + t];
                    const float s = xv + yv, d = xv - yv;
                    const int slot = (r & (RING - 1)) * W + t;
                    p_s[slot]  = s;
                    p_d[slot]  = d;
                    p_ss[slot] = s * s;
                    p_dd[slot] = d * d;
                }
            }
        }
        __syncthreads();

        // ---- vertical blur: threads 0..63, 4 cols (float4) x 4 output rows each ----
        if (t < 64) {
#define VPASS(PB, VB)                                                          \
            {                                                                  \
                float4 a0 = make_float4(0.f, 0.f, 0.f, 0.f);                   \
                float4 a1 = a0, a2 = a0, a3 = a0;                              \
                _Pragma("unroll")                                              \
                for (int k = 0; k < 14; k++) {                                 \
                    const float4 p =                                           \
                        ((const float4*)(PB))[((o0 + k) & (RING - 1)) * 64 + t]; \
                    if (k <= 10)           a0 = f4fma(G[k],     p, a0);        \
                    if (k >= 1 && k <= 11) a1 = f4fma(G[k - 1], p, a1);        \
                    if (k >= 2 && k <= 12) a2 = f4fma(G[k - 2], p, a2);        \
                    if (k >= 3)            a3 = f4fma(G[k - 3], p, a3);        \
                }                                                              \
                ((float4*)(VB))[0 * 64 + t] = a0;                              \
                ((float4*)(VB))[1 * 64 + t] = a1;                              \
                ((float4*)(VB))[2 * 64 + t] = a2;                              \
                ((float4*)(VB))[3 * 64 + t] = a3;                              \
            }
            VPASS(p_s,  v_s)
            VPASS(p_d,  v_d)
            VPASS(p_ss, v_ss)
            VPASS(p_dd, v_dd)
#undef VPASS
        }
        __syncthreads();

        // ---- horizontal blur + SSIM: thread -> (row rr, cols 4g..4g+3) ----
        const int orow = o0 + rr;
        if (g < 62 && orow < OW) {
            float ms[4], md[4], mss[4], mdd[4];
#define HPASS(VB, OUT)                                                         \
            {                                                                  \
                const float4* vp = (const float4*)(VB) + rr * 64 + g;          \
                const float4 A = vp[0], B = vp[1], Cc = vp[2], D = vp[3];      \
                const float w[16] = {A.x, A.y, A.z, A.w, B.x, B.y, B.z, B.w,   \
                                     Cc.x, Cc.y, Cc.z, Cc.w, D.x, D.y, D.z, D.w}; \
                _Pragma("unroll")                                              \
                for (int j = 0; j < 4; j++) {                                  \
                    float sv = 0.0f;                                           \
                    _Pragma("unroll")                                          \
                    for (int k = 0; k < 11; k++)                               \
                        sv = fmaf(G[k], w[j + k], sv);                         \
                    OUT[j] = sv;                                               \
                }                                                              \
            }
            HPASS(v_s,  ms)
            HPASS(v_d,  md)
            HPASS(v_ss, mss)
            HPASS(v_dd, mdd)
#undef HPASS
            const int c0 = g * 4;
            #pragma unroll
            for (int j = 0; j < 4; j++) {
                if (c0 + j < OW) {
                    const float a = ms[j] * ms[j];
                    const float b = md[j] * md[j];
                    const float mxmy2  = (a - b) * 0.5f;              // 2*mx*my
                    const float mx2py2 = (a + b) * 0.5f;              // mx^2+my^2
                    const float cov2   = (mss[j] - mdd[j]) * 0.5f - mxmy2;  // 2*cov
                    const float varsum = (mss[j] + mdd[j]) * 0.5f - mx2py2; // vx+vy
                    const float num = (mxmy2 + C1) * (cov2 + C2);
                    const float den = (mx2py2 + C1) * (varsum + C2);
                    acc += __fdividef(num, den);
                }
            }
        }
    }

    // ---- block reduction ----
    __syncthreads();
    #pragma unroll
    for (int o = 16; o > 0; o >>= 1)
        acc += __shfl_down_sync(0xffffffffu, acc, o);
    if ((t & 31) == 0) red[t >> 5] = acc;
    __syncthreads();
    if (t < 8) {
        float v = red[t];
        #pragma unroll
        for (int o = 4; o > 0; o >>= 1)
            v += __shfl_down_sync(0xffu, v, o);
        if (t == 0) d_partials[blockIdx.y * NSTRIPS + blockIdx.x] = v;
    }
}

__global__ void ssim_final(float* __restrict__ out, int nblocks, double total) {
    __shared__ double red[256];
    const int t = threadIdx.x;
    double s = 0.0;
    for (int i = t; i < nblocks; i += 256) s += (double)d_partials[i];
    red[t] = s;
    __syncthreads();
    #pragma unroll
    for (int o = 128; o > 0; o >>= 1) {
        if (t < o) red[t] += red[t + o];
        __syncthreads();
    }
    if (t == 0) out[0] = (float)(1.0 - red[0] / total);
}

extern "C" void kernel_launch(void* const* d_in, const int* in_sizes, int n_in,
                              void* d_out, int out_size) {
    const float* X = (const float*)d_in[0];
    const float* Y = (const float*)d_in[1];
    const int nimg = in_sizes[0] / IMGPIX;   // 16*31 = 496

    const int smem_bytes = (20480 + 32) * 4; // 82,048 B
    cudaFuncSetAttribute(ssim_main, cudaFuncAttributeMaxDynamicSharedMemorySize,
                         smem_bytes);

    dim3 grid(NSTRIPS, nimg);
    ssim_main<<<grid, 256, smem_bytes>>>(X, Y);
    ssim_final<<<1, 256>>>((float*)d_out, NSTRIPS * nimg,
                           (double)nimg * (double)OW * (double)OW);
}

// round 2
// speedup vs baseline: 1.6228x; 1.6228x over previous
#include <cuda_runtime.h>

#define W       256
#define IMGPIX  65536
#define OW      246
#define STRIP   44
#define NSTRIPS 6

// per-block partial sums; 6*496 = 2976 used, padded region stays zero-initialized
__device__ float d_partials[3072];

__global__ __launch_bounds__(256, 2)
void ssim_main(const float* __restrict__ X, const float* __restrict__ Y) {
    // 11-tap gaussian, sigma=1.5 (torchmetrics default), normalized
    constexpr float G[11] = {
        0.00102838f, 0.00759876f, 0.03600077f, 0.10936069f, 0.21300554f,
        0.26601173f,
        0.21300554f, 0.10936069f, 0.03600077f, 0.00759876f, 0.00102838f
    };
    constexpr float C1 = 1e-4f;   // (0.01*1)^2
    constexpr float C2 = 9e-4f;   // (0.03*1)^2

    __shared__ float v_s [4 * W];   // vertical-blurred rows: 4 rows x 256 cols
    __shared__ float v_d [4 * W];
    __shared__ float v_ss[4 * W];
    __shared__ float v_dd[4 * W];
    __shared__ float red[8];

    const int t   = threadIdx.x;
    const int img = blockIdx.y;
    const int r0  = blockIdx.x * STRIP;
    const int rows = min(STRIP, OW - r0);

    const float* __restrict__ x = X + (size_t)img * IMGPIX + t;
    const float* __restrict__ y = Y + (size_t)img * IMGPIX + t;

    // register sliding windows: rows o0 .. o0+13 of this thread's column
    float ws[14], wd[14], wss[14], wdd[14];

    // prologue: rows r0 .. r0+13 (all < 256)
    #pragma unroll
    for (int i = 0; i < 14; i++) {
        const float xv = x[(r0 + i) * W];
        const float yv = y[(r0 + i) * W];
        const float s = xv + yv, d = xv - yv;
        ws[i] = s; wd[i] = d; wss[i] = s * s; wdd[i] = d * d;
    }

    float acc = 0.0f;
    const int g  = t & 63;   // column group (4 cols) for horizontal phase
    const int rr = t >> 6;   // row within 4-row group

    for (int g0 = 0; g0 < rows; g0 += 4) {
        const int o0 = r0 + g0;   // first output row of this group

        // prefetch next group's 4 input rows (o0+14 .. o0+17), clamped
        float px[4], py[4];
        #pragma unroll
        for (int i = 0; i < 4; i++) {
            const int r = min(o0 + 14 + i, 255);
            px[i] = x[r * W];
            py[i] = y[r * W];
        }

        // ---- vertical blur (all 256 threads, 1 col x 4 rows x 4 ch) ----
        #pragma unroll
        for (int j = 0; j < 4; j++) {
            float as = 0.f, ad = 0.f, ass = 0.f, add = 0.f;
            #pragma unroll
            for (int k = 0; k < 11; k++) {
                as  = fmaf(G[k], ws [j + k], as);
                ad  = fmaf(G[k], wd [j + k], ad);
                ass = fmaf(G[k], wss[j + k], ass);
                add = fmaf(G[k], wdd[j + k], add);
            }
            v_s [j * W + t] = as;
            v_d [j * W + t] = ad;
            v_ss[j * W + t] = ass;
            v_dd[j * W + t] = add;
        }
        __syncthreads();

        // ---- horizontal blur + SSIM: thread -> (row rr, cols 4g..4g+3) ----
        const int orow = o0 + rr;
        if (g < 62 && orow < OW) {
            float ms[4], md[4], mss[4], mdd[4];
#define HPASS(VB, OUT)                                                         \
            {                                                                  \
                const float4* vp = (const float4*)(VB) + rr * 64 + g;          \
                const float4 A = vp[0], B = vp[1], Cc = vp[2], D = vp[3];      \
                const float w[16] = {A.x, A.y, A.z, A.w, B.x, B.y, B.z, B.w,   \
                                     Cc.x, Cc.y, Cc.z, Cc.w, D.x, D.y, D.z, D.w}; \
                _Pragma("unroll")                                              \
                for (int j = 0; j < 4; j++) {                                  \
                    float sv = 0.0f;                                           \
                    _Pragma("unroll")                                          \
                    for (int k = 0; k < 11; k++)                               \
                        sv = fmaf(G[k], w[j + k], sv);                         \
                    OUT[j] = sv;                                               \
                }                                                              \
            }
            HPASS(v_s,  ms)
            HPASS(v_d,  md)
            HPASS(v_ss, mss)
            HPASS(v_dd, mdd)
#undef HPASS
            const int c0 = g * 4;
            #pragma unroll
            for (int j = 0; j < 4; j++) {
                if (c0 + j < OW) {
                    const float a = ms[j] * ms[j];
                    const float b = md[j] * md[j];
                    const float mxmy2  = (a - b) * 0.5f;                    // 2*mx*my
                    const float mx2py2 = (a + b) * 0.5f;                    // mx^2+my^2
                    const float cov2   = (mss[j] - mdd[j]) * 0.5f - mxmy2;  // 2*cov
                    const float varsum = (mss[j] + mdd[j]) * 0.5f - mx2py2; // vx+vy
                    const float num = (mxmy2 + C1) * (cov2 + C2);
                    const float den = (mx2py2 + C1) * (varsum + C2);
                    acc += __fdividef(num, den);
                }
            }
        }
        __syncthreads();

        // ---- shift windows by 4, insert prefetched rows ----
        #pragma unroll
        for (int i = 0; i < 10; i++) {
            ws[i] = ws[i + 4]; wd[i] = wd[i + 4];
            wss[i] = wss[i + 4]; wdd[i] = wdd[i + 4];
        }
        #pragma unroll
        for (int i = 0; i < 4; i++) {
            const float s = px[i] + py[i], d = px[i] - py[i];
            ws[10 + i] = s; wd[10 + i] = d;
            wss[10 + i] = s * s; wdd[10 + i] = d * d;
        }
    }

    // ---- block reduction ----
    #pragma unroll
    for (int o = 16; o > 0; o >>= 1)
        acc += __shfl_down_sync(0xffffffffu, acc, o);
    if ((t & 31) == 0) red[t >> 5] = acc;
    __syncthreads();
    if (t < 8) {
        float v = red[t];
        #pragma unroll
        for (int o = 4; o > 0; o >>= 1)
            v += __shfl_down_sync(0xffu, v, o);
        if (t == 0) d_partials[blockIdx.y * NSTRIPS + blockIdx.x] = v;
    }
}

__global__ void ssim_final(float* __restrict__ out, double total) {
    __shared__ double red[256];
    const int t = threadIdx.x;
    const float4* p = (const float4*)d_partials;   // 3072 floats = 768 float4
    double s = 0.0;
    #pragma unroll
    for (int i = 0; i < 3; i++) {
        const float4 v = p[t + i * 256];
        s += (double)v.x + (double)v.y + (double)v.z + (double)v.w;
    }
    red[t] = s;
    __syncthreads();
    #pragma unroll
    for (int o = 128; o > 0; o >>= 1) {
        if (t < o) red[t] += red[t + o];
        __syncthreads();
    }
    if (t == 0) out[0] = (float)(1.0 - red[0] / total);
}

extern "C" void kernel_launch(void* const* d_in, const int* in_sizes, int n_in,
                              void* d_out, int out_size) {
    const float* X = (const float*)d_in[0];
    const float* Y = (const float*)d_in[1];
    const int nimg = in_sizes[0] / IMGPIX;   // 16*31 = 496

    dim3 grid(NSTRIPS, nimg);
    ssim_main<<<grid, 256>>>(X, Y);
    ssim_final<<<1, 256>>>((float*)d_out,
                           (double)nimg * (double)OW * (double)OW);
}